// round 2
// baseline (speedup 1.0000x reference)
#include <cuda_runtime.h>
#include <math.h>
#include <stdint.h>

// Problem constants
#define NB 32            // batch
#define TT 1024          // timesteps
#define DD 512           // input dim
#define HH 512           // hidden dim
#define G4 2048          // 4*H
#define MROWS (NB * TT)  // 32768

// Recurrent kernel config
#define RBLOCKS 128      // persistent blocks, 1 per SM (<=148)
#define RTHREADS 256
#define JPB 4            // h-columns per block (128*4 = 512 = HH)
#define CPB 16           // gate columns per block (4 gates * JPB)
#define KSPLIT 8         // k-split warps
#define KCHUNK (HH / KSPLIT)  // 64

// Scratch (device globals; no cudaMalloc allowed)
__device__ float g_xw[(size_t)MROWS * G4];   // 268 MB: x @ Wx + b, layout [n*T + t][4H]
__device__ float g_hT[2][HH * NB];           // ping-pong h, TRANSPOSED: [f][n]
__device__ unsigned g_count;                 // barrier arrive counter (self-resetting)
__device__ unsigned g_sense;                 // barrier sense (monotonic)

// ---------------------------------------------------------------------------
// Phase 1: xW = x @ Wx + b.  M=32768, N=2048, K=512. fp32 SIMT tiled SGEMM.
// BM=BN=128, BK=8, 256 threads, 8x8 register tile per thread.
// ---------------------------------------------------------------------------
__global__ void __launch_bounds__(256) gemm_xw_kernel(const float* __restrict__ A,
                                                      const float* __restrict__ B,
                                                      const float* __restrict__ bias)
{
    __shared__ float As[8][128];   // transposed A tile: [k][m]
    __shared__ float Bs[8][128];   // [k][n]

    const int tid = threadIdx.x;
    const int bm = blockIdx.y;
    const int bn = blockIdx.x;
    const int tr = tid >> 4;          // 0..15
    const int tc = tid & 15;          // 0..15
    const int arow = tid >> 1;        // 0..127
    const int acol = (tid & 1) * 4;   // 0 or 4
    const int brow = tid >> 5;        // 0..7
    const int bcol = (tid & 31) * 4;  // 0..124

    const float* Ab = A + (size_t)bm * 128 * DD;
    const float* Bb = B + (size_t)bn * 128;

    float acc[8][8];
#pragma unroll
    for (int i = 0; i < 8; i++)
#pragma unroll
        for (int j = 0; j < 8; j++) acc[i][j] = 0.0f;

    for (int k0 = 0; k0 < DD; k0 += 8) {
        float4 a4 = *(const float4*)(Ab + (size_t)arow * DD + k0 + acol);
        As[acol + 0][arow] = a4.x;
        As[acol + 1][arow] = a4.y;
        As[acol + 2][arow] = a4.z;
        As[acol + 3][arow] = a4.w;
        *(float4*)&Bs[brow][bcol] =
            *(const float4*)(Bb + (size_t)(k0 + brow) * G4 + bcol);
        __syncthreads();

#pragma unroll
        for (int kk = 0; kk < 8; kk++) {
            float4 ra0 = *(const float4*)&As[kk][tr * 8];
            float4 ra1 = *(const float4*)&As[kk][tr * 8 + 4];
            float4 rb0 = *(const float4*)&Bs[kk][tc * 8];
            float4 rb1 = *(const float4*)&Bs[kk][tc * 8 + 4];
            float ra[8] = {ra0.x, ra0.y, ra0.z, ra0.w, ra1.x, ra1.y, ra1.z, ra1.w};
            float rb[8] = {rb0.x, rb0.y, rb0.z, rb0.w, rb1.x, rb1.y, rb1.z, rb1.w};
#pragma unroll
            for (int i = 0; i < 8; i++)
#pragma unroll
                for (int j = 0; j < 8; j++)
                    acc[i][j] = fmaf(ra[i], rb[j], acc[i][j]);
        }
        __syncthreads();
    }

    // epilogue: += bias, write to g_xw
    float bv[8];
    {
        const float* bp = bias + (size_t)bn * 128 + tc * 8;
#pragma unroll
        for (int j = 0; j < 8; j++) bv[j] = bp[j];
    }
#pragma unroll
    for (int i = 0; i < 8; i++) {
        size_t row = (size_t)bm * 128 + tr * 8 + i;
        float* Crow = g_xw + row * G4 + (size_t)bn * 128 + tc * 8;
        float4 v0, v1;
        v0.x = acc[i][0] + bv[0]; v0.y = acc[i][1] + bv[1];
        v0.z = acc[i][2] + bv[2]; v0.w = acc[i][3] + bv[3];
        v1.x = acc[i][4] + bv[4]; v1.y = acc[i][5] + bv[5];
        v1.z = acc[i][6] + bv[6]; v1.w = acc[i][7] + bv[7];
        *(float4*)Crow = v0;
        *(float4*)(Crow + 4) = v1;
    }
}

// ---------------------------------------------------------------------------
// Accurate-but-fast activations (pure fp32 path; ~1e-7 rel err)
// ---------------------------------------------------------------------------
__device__ __forceinline__ float sigmoid_f(float x)
{
    float t = __expf(-fabsf(x));
    float inv = 1.0f / (1.0f + t);
    return (x >= 0.0f) ? inv : t * inv;
}

__device__ __forceinline__ float tanh_f(float x)
{
    float e = __expf(-2.0f * fabsf(x));
    float r = (1.0f - e) / (1.0f + e);
    return (x >= 0.0f) ? r : -r;
}

// ---------------------------------------------------------------------------
// Replay-safe grid barrier. Counter self-resets; sense is monotonic and each
// launch reads its base before arriving at barrier #1, so graph replays work.
// All threads must call __threadfence() (release) before this if they wrote
// global data other blocks will read.
// ---------------------------------------------------------------------------
__device__ __forceinline__ void grid_barrier(unsigned target)
{
    __syncthreads();
    if (threadIdx.x == 0) {
        unsigned old = atomicAdd(&g_count, 1u);
        if (old == RBLOCKS - 1) {
            atomicExch(&g_count, 0u);
            __threadfence();
            atomicAdd(&g_sense, 1u);
        } else {
            while ((int)(*(volatile unsigned*)&g_sense - target) < 0) { }
            __threadfence();
        }
    }
    __syncthreads();
}

// ---------------------------------------------------------------------------
// Phase 2: persistent recurrent kernel.
// Block b owns h-columns j0..j0+3 (j0 = 4b) -> 16 gate columns.
// Per step: load h_{t-1} (transposed) into smem, 8-warp K-split GEMM fragment
// (32 x 16 x 512) with 4x4 register tiles, reduce, gates, write h_t + out.
// ---------------------------------------------------------------------------
#define SM_W    0                       // w_s   [512][16]  = 8192
#define SM_HT   (SM_W + 512 * 16)       // hT_s  [512][32]  = 16384
#define SM_RED  (SM_HT + 512 * 32)      // red   [8][512]   = 4096
#define SM_A    (SM_RED + 8 * 512)      // a_s   [512]
#define SM_XW   (SM_A + 512)            // xw_s  [512]  (n*16 + g*4 + jl)
#define SM_C    (SM_XW + 512)           // c_s   [128]  (n*4 + jl)
#define SM_FLOATS (SM_C + 128)          // 29824 floats = 119296 B
#define SMEM_BYTES (SM_FLOATS * 4)

__global__ void __launch_bounds__(RTHREADS, 1)
lstm_rec_kernel(const float* __restrict__ h0,
                const float* __restrict__ Wh,
                float* __restrict__ out)
{
    extern __shared__ float sm[];
    float* w_s  = sm + SM_W;
    float* hT_s = sm + SM_HT;
    float* red  = sm + SM_RED;
    float* a_s  = sm + SM_A;
    float* xw_s = sm + SM_XW;
    float* c_s  = sm + SM_C;

    const int tid = threadIdx.x;
    const int bid = blockIdx.x;
    const int j0  = bid * JPB;

    // Barrier base: must be read before this block arrives at any barrier.
    const unsigned sense0 = *(volatile unsigned*)&g_sense;
    unsigned nbar = 0;

    // Load Wh slice into smem: w_s[k][c], c = g*4 + jl, gcol = g*512 + j0 + jl.
    for (int it = tid; it < 512 * 4; it += RTHREADS) {
        int k = it >> 2, g = it & 3;
        float4 w4 = *(const float4*)(Wh + (size_t)k * G4 + g * 512 + j0);
        *(float4*)&w_s[k * CPB + g * 4] = w4;
    }

    // Init g_hT[0] from h0 (h0 is [n][f], we store [f][n]); zero c.
    {
        int idx = bid * RTHREADS + tid;
        if (idx < HH * NB) {
            int n = idx & 31, f = idx >> 5;
            g_hT[0][idx] = h0[(size_t)n * HH + f];
        }
    }
    if (tid < NB * JPB) c_s[tid] = 0.0f;
    __threadfence();
    grid_barrier(sense0 + (++nbar));

    // Compute-thread geometry (8 k-split warps, 4x4 output tiles)
    const int kg   = tid >> 5;
    const int lane = tid & 31;
    const int jj   = lane >> 3;  // 0..3 -> cols 4jj..4jj+3
    const int ii   = lane & 7;   // 0..7 -> rows 4ii..4ii+3
    const float* wp0 = &w_s[(kg * KCHUNK) * CPB + 4 * jj];

    for (int t = 0; t < TT; t++) {
        // Load h_{t-1} (transposed, fresh from L2 — other SMs wrote it)
        const float* hsrc = g_hT[t & 1];
#pragma unroll
        for (int c = 0; c < 16; c++) {
            int w = c * 1024 + tid * 4;
            float4 v = __ldcg((const float4*)(hsrc + w));
            *(float4*)&hT_s[w] = v;
        }
        // Load this step's xW fragment: xw_s[n*16 + g*4 + jl]
        if (tid < 128) {
            int n = tid >> 2, g = tid & 3;
            const float* p = g_xw + ((size_t)n * TT + t) * G4 + g * 512 + j0;
            float4 v = *(const float4*)p;
            *(float4*)&xw_s[n * CPB + g * 4] = v;
        }
        __syncthreads();

        // GEMM fragment: partials for 4x4 tile over K-chunk
        float acc[4][4];
#pragma unroll
        for (int a = 0; a < 4; a++)
#pragma unroll
            for (int b = 0; b < 4; b++) acc[a][b] = 0.0f;

        const float* hp = &hT_s[(kg * KCHUNK) * NB + 4 * ii];
        const float* wp = wp0;
#pragma unroll 4
        for (int k = 0; k < KCHUNK; k++) {
            float4 h4 = *(const float4*)(hp + k * NB);
            float4 w4 = *(const float4*)(wp + k * CPB);
            float ha[4] = {h4.x, h4.y, h4.z, h4.w};
            float wb[4] = {w4.x, w4.y, w4.z, w4.w};
#pragma unroll
            for (int a = 0; a < 4; a++)
#pragma unroll
                for (int b = 0; b < 4; b++)
                    acc[a][b] = fmaf(ha[a], wb[b], acc[a][b]);
        }
#pragma unroll
        for (int a = 0; a < 4; a++) {
            float4 v = {acc[a][0], acc[a][1], acc[a][2], acc[a][3]};
            *(float4*)&red[kg * 512 + (4 * ii + a) * CPB + 4 * jj] = v;
        }
        __syncthreads();

        // Reduce k-split partials + xW
        for (int o = tid; o < 512; o += RTHREADS) {
            float s = xw_s[o];
#pragma unroll
            for (int g = 0; g < KSPLIT; g++) s += red[g * 512 + o];
            a_s[o] = s;
        }
        __syncthreads();

        // Gates + state update (one thread per (n, jl))
        if (tid < 128) {
            int n = tid >> 2, jl = tid & 3;
            const float* ap = &a_s[n * CPB + jl];
            float gi = sigmoid_f(ap[0]);    // g=0: i
            float gf = sigmoid_f(ap[4]);    // g=1: f
            float go = sigmoid_f(ap[8]);    // g=2: o
            float gg = tanh_f(ap[12]);      // g=3: g
            float cold = c_s[tid];
            float cnew = fmaf(gf, cold, gi * gg);
            c_s[tid] = cnew;
            float hnew = go * tanh_f(cnew);
            g_hT[(t + 1) & 1][(j0 + jl) * NB + n] = hnew;
            out[((size_t)n * TT + t) * HH + j0 + jl] = hnew;
        }
        __threadfence();
        grid_barrier(sense0 + (++nbar));
    }
}

// ---------------------------------------------------------------------------
// kernel_launch
// ---------------------------------------------------------------------------
extern "C" void kernel_launch(void* const* d_in, const int* in_sizes, int n_in,
                              void* d_out, int out_size)
{
    const float* x  = (const float*)d_in[0];  // (32, 1024, 512)
    const float* h0 = (const float*)d_in[1];  // (32, 512)
    const float* Wx = (const float*)d_in[2];  // (512, 2048)
    const float* Wh = (const float*)d_in[3];  // (512, 2048)
    const float* b  = (const float*)d_in[4];  // (2048,)
    float* out = (float*)d_out;               // (32, 1024, 512)

    (void)in_sizes; (void)n_in; (void)out_size;

    cudaFuncSetAttribute(lstm_rec_kernel,
                         cudaFuncAttributeMaxDynamicSharedMemorySize, SMEM_BYTES);

    dim3 g1(G4 / 128, MROWS / 128);  // (16, 256)
    gemm_xw_kernel<<<g1, 256>>>(x, Wx, b);
    lstm_rec_kernel<<<RBLOCKS, RTHREADS, SMEM_BYTES>>>(h0, Wh, out);
}

// round 3
// speedup vs baseline: 1.0757x; 1.0757x over previous
#include <cuda_runtime.h>
#include <cuda_bf16.h>
#include <math.h>
#include <stdint.h>

// Problem constants
#define NB 32            // batch
#define TT 1024          // timesteps
#define DD 512           // input dim
#define HH 512           // hidden dim
#define G4 2048          // 4*H
#define MROWS (NB * TT)  // 32768

// Recurrent kernel config
#define RBLOCKS 128      // persistent blocks, 1 per SM (<=148)
#define RTHREADS 256
#define JPB 4            // h-columns per block (128*4 = 512 = HH)
#define CPB 16           // gate columns per block (4 gates * JPB)
#define KSPLIT 8         // k-split warps
#define KCHUNK (HH / KSPLIT)  // 64

// Scratch (device globals; no cudaMalloc allowed)
__device__ float g_xw[(size_t)MROWS * G4];   // 268 MB: x @ Wx + b
__device__ float g_hT[2][HH * NB];           // ping-pong h, TRANSPOSED: [f][n]
__device__ unsigned g_count;                 // barrier arrive counter (self-resetting)
__device__ unsigned g_sense;                 // barrier sense (monotonic)

// bf16 hi/lo split buffers for tensor-core phase 1
__device__ __nv_bfloat16 g_xhi[(size_t)MROWS * DD];
__device__ __nv_bfloat16 g_xlo[(size_t)MROWS * DD];
__device__ __nv_bfloat16 g_whi[(size_t)DD * G4];
__device__ __nv_bfloat16 g_wlo[(size_t)DD * G4];

// ---------------------------------------------------------------------------
// Split fp32 -> bf16 hi + bf16 lo (residual). hi+lo ~ 17-bit mantissa accuracy.
// ---------------------------------------------------------------------------
__device__ __forceinline__ void split1(float v, __nv_bfloat16& h, __nv_bfloat16& l)
{
    h = __float2bfloat16(v);
    l = __float2bfloat16(v - __bfloat162float(h));
}

__global__ void split_x_kernel()
{
    extern __shared__ char _dummy_sx[];
    const float* src;
    // src set below via symbol-free path: passed through global pointer trick is
    // avoided; instead split kernels take src as parameter (see variants below).
}

// parameterized split kernels writing to fixed globals
__global__ void __launch_bounds__(256) split_kernel_x(const float* __restrict__ src)
{
    size_t i = (size_t)blockIdx.x * blockDim.x + threadIdx.x;   // float4 index
    size_t n4 = (size_t)MROWS * DD / 4;
    if (i >= n4) return;
    float4 v = ((const float4*)src)[i];
    __nv_bfloat16 h0, h1, h2, h3, l0, l1, l2, l3;
    split1(v.x, h0, l0); split1(v.y, h1, l1);
    split1(v.z, h2, l2); split1(v.w, h3, l3);
    ((__nv_bfloat162*)g_xhi)[2 * i]     = __nv_bfloat162(h0, h1);
    ((__nv_bfloat162*)g_xhi)[2 * i + 1] = __nv_bfloat162(h2, h3);
    ((__nv_bfloat162*)g_xlo)[2 * i]     = __nv_bfloat162(l0, l1);
    ((__nv_bfloat162*)g_xlo)[2 * i + 1] = __nv_bfloat162(l2, l3);
}

__global__ void __launch_bounds__(256) split_kernel_w(const float* __restrict__ src)
{
    size_t i = (size_t)blockIdx.x * blockDim.x + threadIdx.x;
    size_t n4 = (size_t)DD * G4 / 4;
    if (i >= n4) return;
    float4 v = ((const float4*)src)[i];
    __nv_bfloat16 h0, h1, h2, h3, l0, l1, l2, l3;
    split1(v.x, h0, l0); split1(v.y, h1, l1);
    split1(v.z, h2, l2); split1(v.w, h3, l3);
    ((__nv_bfloat162*)g_whi)[2 * i]     = __nv_bfloat162(h0, h1);
    ((__nv_bfloat162*)g_whi)[2 * i + 1] = __nv_bfloat162(h2, h3);
    ((__nv_bfloat162*)g_wlo)[2 * i]     = __nv_bfloat162(l0, l1);
    ((__nv_bfloat162*)g_wlo)[2 * i + 1] = __nv_bfloat162(l2, l3);
}

// ---------------------------------------------------------------------------
// PTX wrappers
// ---------------------------------------------------------------------------
__device__ __forceinline__ void ldsm_x4(uint32_t& r0, uint32_t& r1, uint32_t& r2,
                                        uint32_t& r3, const void* p)
{
    uint32_t a = (uint32_t)__cvta_generic_to_shared(p);
    asm volatile("ldmatrix.sync.aligned.m8n8.x4.shared.b16 {%0,%1,%2,%3}, [%4];"
                 : "=r"(r0), "=r"(r1), "=r"(r2), "=r"(r3) : "r"(a));
}

__device__ __forceinline__ void ldsm_x4_t(uint32_t& r0, uint32_t& r1, uint32_t& r2,
                                          uint32_t& r3, const void* p)
{
    uint32_t a = (uint32_t)__cvta_generic_to_shared(p);
    asm volatile("ldmatrix.sync.aligned.m8n8.x4.trans.shared.b16 {%0,%1,%2,%3}, [%4];"
                 : "=r"(r0), "=r"(r1), "=r"(r2), "=r"(r3) : "r"(a));
}

__device__ __forceinline__ void mma_bf16(float* c, const uint32_t* a,
                                         uint32_t b0, uint32_t b1)
{
    asm volatile(
        "mma.sync.aligned.m16n8k16.row.col.f32.bf16.bf16.f32 "
        "{%0,%1,%2,%3},{%4,%5,%6,%7},{%8,%9},{%0,%1,%2,%3};"
        : "+f"(c[0]), "+f"(c[1]), "+f"(c[2]), "+f"(c[3])
        : "r"(a[0]), "r"(a[1]), "r"(a[2]), "r"(a[3]), "r"(b0), "r"(b1));
}

// ---------------------------------------------------------------------------
// Phase 1 GEMM on tensor cores (bf16 split, fp32 accumulate).
// C[M=32768, N=2048] = Ah*Bh + Ah*Bl + Al*Bh + bias.
// Block tile 64x128xBK32, 8 warps (2x4), warp tile 32x32 (2 m16 x 4 n8).
// ---------------------------------------------------------------------------
#define P1_SA 40    // A smem row stride (bf16 elems): 80B, conflict-free ldmatrix
#define P1_SB 136   // B smem row stride: 272B = 16 mod 128, conflict-free trans

__global__ void __launch_bounds__(256, 2) gemm_xw_mma(const float* __restrict__ bias)
{
    __shared__ __nv_bfloat16 Ah[64 * P1_SA];
    __shared__ __nv_bfloat16 Al[64 * P1_SA];
    __shared__ __nv_bfloat16 Bh[32 * P1_SB];
    __shared__ __nv_bfloat16 Bl[32 * P1_SB];

    const int tid = threadIdx.x;
    const int bn = blockIdx.x;   // 0..15
    const int bm = blockIdx.y;   // 0..511
    const int warp = tid >> 5;
    const int lane = tid & 31;
    const int wm = (warp >> 2) * 32;  // 0 or 32
    const int wn = (warp & 3) * 32;   // 0,32,64,96

    // global load geometry
    const int arow = tid >> 2;            // 0..63
    const int acol = (tid & 3) * 8;       // 0,8,16,24
    const int brow = tid >> 4;            // 0..15 (two passes, +16)
    const int bcol = (tid & 15) * 8;      // 0..120

    const size_t a_off = (size_t)(bm * 64 + arow) * DD + acol;
    const size_t b_off0 = (size_t)brow * G4 + bn * 128 + bcol;

    float acc[2][4][4];
#pragma unroll
    for (int mi = 0; mi < 2; mi++)
#pragma unroll
        for (int n = 0; n < 4; n++)
#pragma unroll
            for (int q = 0; q < 4; q++) acc[mi][n][q] = 0.0f;

    // ldmatrix source addresses (fixed per thread, k varies)
    const int a_lrow = lane & 15;
    const int a_lcol = (lane >> 4) << 3;

    for (int k0 = 0; k0 < DD; k0 += 32) {
        *(uint4*)&Ah[arow * P1_SA + acol] = *(const uint4*)&g_xhi[a_off + k0];
        *(uint4*)&Al[arow * P1_SA + acol] = *(const uint4*)&g_xlo[a_off + k0];
#pragma unroll
        for (int i = 0; i < 2; i++) {
            size_t go = b_off0 + (size_t)(k0 + i * 16) * G4;
            *(uint4*)&Bh[(brow + i * 16) * P1_SB + bcol] = *(const uint4*)&g_whi[go];
            *(uint4*)&Bl[(brow + i * 16) * P1_SB + bcol] = *(const uint4*)&g_wlo[go];
        }
        __syncthreads();

#pragma unroll
        for (int kk = 0; kk < 32; kk += 16) {
            uint32_t ah[2][4], al[2][4], bh[2][4], bl[2][4];
#pragma unroll
            for (int mi = 0; mi < 2; mi++) {
                const __nv_bfloat16* pa =
                    &Ah[(wm + mi * 16 + a_lrow) * P1_SA + kk + a_lcol];
                ldsm_x4(ah[mi][0], ah[mi][1], ah[mi][2], ah[mi][3], pa);
                const __nv_bfloat16* pl =
                    &Al[(wm + mi * 16 + a_lrow) * P1_SA + kk + a_lcol];
                ldsm_x4(al[mi][0], al[mi][1], al[mi][2], al[mi][3], pl);
            }
#pragma unroll
            for (int g = 0; g < 2; g++) {
                const __nv_bfloat16* pb =
                    &Bh[(kk + a_lrow) * P1_SB + wn + g * 16 + a_lcol];
                ldsm_x4_t(bh[g][0], bh[g][1], bh[g][2], bh[g][3], pb);
                const __nv_bfloat16* pbl =
                    &Bl[(kk + a_lrow) * P1_SB + wn + g * 16 + a_lcol];
                ldsm_x4_t(bl[g][0], bl[g][1], bl[g][2], bl[g][3], pbl);
            }
#pragma unroll
            for (int mi = 0; mi < 2; mi++)
#pragma unroll
                for (int n = 0; n < 4; n++) {
                    uint32_t b0 = bh[n >> 1][(n & 1) * 2];
                    uint32_t b1 = bh[n >> 1][(n & 1) * 2 + 1];
                    uint32_t c0 = bl[n >> 1][(n & 1) * 2];
                    uint32_t c1 = bl[n >> 1][(n & 1) * 2 + 1];
                    mma_bf16(acc[mi][n], ah[mi], b0, b1);  // Ah*Bh
                    mma_bf16(acc[mi][n], ah[mi], c0, c1);  // Ah*Bl
                    mma_bf16(acc[mi][n], al[mi], b0, b1);  // Al*Bh
                }
        }
        __syncthreads();
    }

    // epilogue: add bias, write fp32 to g_xw
    const int r0 = bm * 64 + wm + (lane >> 2);
    const int c0 = bn * 128 + wn + (lane & 3) * 2;
#pragma unroll
    for (int mi = 0; mi < 2; mi++)
#pragma unroll
        for (int n = 0; n < 4; n++) {
            int col = c0 + n * 8;
            float bv0 = bias[col], bv1 = bias[col + 1];
            int row = r0 + mi * 16;
            float2 v0 = {acc[mi][n][0] + bv0, acc[mi][n][1] + bv1};
            float2 v1 = {acc[mi][n][2] + bv0, acc[mi][n][3] + bv1};
            *(float2*)&g_xw[(size_t)row * G4 + col] = v0;
            *(float2*)&g_xw[(size_t)(row + 8) * G4 + col] = v1;
        }
}

// ---------------------------------------------------------------------------
// Accurate-but-fast activations (pure fp32 path)
// ---------------------------------------------------------------------------
__device__ __forceinline__ float sigmoid_f(float x)
{
    float t = __expf(-fabsf(x));
    float inv = 1.0f / (1.0f + t);
    return (x >= 0.0f) ? inv : t * inv;
}

__device__ __forceinline__ float tanh_f(float x)
{
    float e = __expf(-2.0f * fabsf(x));
    float r = (1.0f - e) / (1.0f + e);
    return (x >= 0.0f) ? r : -r;
}

// ---------------------------------------------------------------------------
// Replay-safe grid barrier (counter self-resets; sense monotonic)
// ---------------------------------------------------------------------------
__device__ __forceinline__ void grid_barrier(unsigned target)
{
    __syncthreads();
    if (threadIdx.x == 0) {
        unsigned old = atomicAdd(&g_count, 1u);
        if (old == RBLOCKS - 1) {
            atomicExch(&g_count, 0u);
            __threadfence();
            atomicAdd(&g_sense, 1u);
        } else {
            while ((int)(*(volatile unsigned*)&g_sense - target) < 0) { }
            __threadfence();
        }
    }
    __syncthreads();
}

// ---------------------------------------------------------------------------
// Phase 2: persistent recurrent kernel (unchanged from R2 — passing config)
// ---------------------------------------------------------------------------
#define SM_W    0
#define SM_HT   (SM_W + 512 * 16)
#define SM_RED  (SM_HT + 512 * 32)
#define SM_A    (SM_RED + 8 * 512)
#define SM_XW   (SM_A + 512)
#define SM_C    (SM_XW + 512)
#define SM_FLOATS (SM_C + 128)
#define SMEM_BYTES (SM_FLOATS * 4)

__global__ void __launch_bounds__(RTHREADS, 1)
lstm_rec_kernel(const float* __restrict__ h0,
                const float* __restrict__ Wh,
                float* __restrict__ out)
{
    extern __shared__ float sm[];
    float* w_s  = sm + SM_W;
    float* hT_s = sm + SM_HT;
    float* red  = sm + SM_RED;
    float* a_s  = sm + SM_A;
    float* xw_s = sm + SM_XW;
    float* c_s  = sm + SM_C;

    const int tid = threadIdx.x;
    const int bid = blockIdx.x;
    const int j0  = bid * JPB;

    const unsigned sense0 = *(volatile unsigned*)&g_sense;
    unsigned nbar = 0;

    for (int it = tid; it < 512 * 4; it += RTHREADS) {
        int k = it >> 2, g = it & 3;
        float4 w4 = *(const float4*)(Wh + (size_t)k * G4 + g * 512 + j0);
        *(float4*)&w_s[k * CPB + g * 4] = w4;
    }

    {
        int idx = bid * RTHREADS + tid;
        if (idx < HH * NB) {
            int n = idx & 31, f = idx >> 5;
            g_hT[0][idx] = h0[(size_t)n * HH + f];
        }
    }
    if (tid < NB * JPB) c_s[tid] = 0.0f;
    __threadfence();
    grid_barrier(sense0 + (++nbar));

    const int kg   = tid >> 5;
    const int lane = tid & 31;
    const int jj   = lane >> 3;
    const int ii   = lane & 7;
    const float* wp0 = &w_s[(kg * KCHUNK) * CPB + 4 * jj];

    for (int t = 0; t < TT; t++) {
        const float* hsrc = g_hT[t & 1];
#pragma unroll
        for (int c = 0; c < 16; c++) {
            int w = c * 1024 + tid * 4;
            float4 v = __ldcg((const float4*)(hsrc + w));
            *(float4*)&hT_s[w] = v;
        }
        if (tid < 128) {
            int n = tid >> 2, g = tid & 3;
            const float* p = g_xw + ((size_t)n * TT + t) * G4 + g * 512 + j0;
            float4 v = *(const float4*)p;
            *(float4*)&xw_s[n * CPB + g * 4] = v;
        }
        __syncthreads();

        float acc[4][4];
#pragma unroll
        for (int a = 0; a < 4; a++)
#pragma unroll
            for (int b = 0; b < 4; b++) acc[a][b] = 0.0f;

        const float* hp = &hT_s[(kg * KCHUNK) * NB + 4 * ii];
        const float* wp = wp0;
#pragma unroll 4
        for (int k = 0; k < KCHUNK; k++) {
            float4 h4 = *(const float4*)(hp + k * NB);
            float4 w4 = *(const float4*)(wp + k * CPB);
            float ha[4] = {h4.x, h4.y, h4.z, h4.w};
            float wb[4] = {w4.x, w4.y, w4.z, w4.w};
#pragma unroll
            for (int a = 0; a < 4; a++)
#pragma unroll
                for (int b = 0; b < 4; b++)
                    acc[a][b] = fmaf(ha[a], wb[b], acc[a][b]);
        }
#pragma unroll
        for (int a = 0; a < 4; a++) {
            float4 v = {acc[a][0], acc[a][1], acc[a][2], acc[a][3]};
            *(float4*)&red[kg * 512 + (4 * ii + a) * CPB + 4 * jj] = v;
        }
        __syncthreads();

        for (int o = tid; o < 512; o += RTHREADS) {
            float s = xw_s[o];
#pragma unroll
            for (int g = 0; g < KSPLIT; g++) s += red[g * 512 + o];
            a_s[o] = s;
        }
        __syncthreads();

        if (tid < 128) {
            int n = tid >> 2, jl = tid & 3;
            const float* ap = &a_s[n * CPB + jl];
            float gi = sigmoid_f(ap[0]);
            float gf = sigmoid_f(ap[4]);
            float go = sigmoid_f(ap[8]);
            float gg = tanh_f(ap[12]);
            float cold = c_s[tid];
            float cnew = fmaf(gf, cold, gi * gg);
            c_s[tid] = cnew;
            float hnew = go * tanh_f(cnew);
            g_hT[(t + 1) & 1][(j0 + jl) * NB + n] = hnew;
            out[((size_t)n * TT + t) * HH + j0 + jl] = hnew;
        }
        __threadfence();
        grid_barrier(sense0 + (++nbar));
    }
}

// ---------------------------------------------------------------------------
// kernel_launch
// ---------------------------------------------------------------------------
extern "C" void kernel_launch(void* const* d_in, const int* in_sizes, int n_in,
                              void* d_out, int out_size)
{
    const float* x  = (const float*)d_in[0];  // (32, 1024, 512)
    const float* h0 = (const float*)d_in[1];  // (32, 512)
    const float* Wx = (const float*)d_in[2];  // (512, 2048)
    const float* Wh = (const float*)d_in[3];  // (512, 2048)
    const float* b  = (const float*)d_in[4];  // (2048,)
    float* out = (float*)d_out;               // (32, 1024, 512)

    (void)in_sizes; (void)n_in; (void)out_size;

    cudaFuncSetAttribute(lstm_rec_kernel,
                         cudaFuncAttributeMaxDynamicSharedMemorySize, SMEM_BYTES);

    // Phase 1: split fp32 -> bf16 hi/lo, then tensor-core GEMM
    size_t nx4 = (size_t)MROWS * DD / 4;   // 4,194,304
    size_t nw4 = (size_t)DD * G4 / 4;      // 262,144
    split_kernel_x<<<(unsigned)((nx4 + 255) / 256), 256>>>(x);
    split_kernel_w<<<(unsigned)((nw4 + 255) / 256), 256>>>(Wx);

    dim3 g1(G4 / 128, MROWS / 64);  // (16, 512)
    gemm_xw_mma<<<g1, 256>>>(b);

    // Phase 2: persistent recurrence
    lstm_rec_kernel<<<RBLOCKS, RTHREADS, SMEM_BYTES>>>(h0, Wh, out);
}

// round 4
// speedup vs baseline: 1.7541x; 1.6306x over previous
#include <cuda_runtime.h>
#include <cuda_bf16.h>
#include <math.h>
#include <stdint.h>

// Problem constants
#define NB 32            // batch
#define TT 1024          // timesteps
#define DD 512           // input dim
#define HH 512           // hidden dim
#define G4 2048          // 4*H
#define MROWS (NB * TT)  // 32768

// Recurrent kernel config
#define RBLOCKS 128      // persistent blocks, 1 per SM
#define RTHREADS 256
#define JPB 4            // h-columns per block
#define CPB 16           // gate columns per block

// Scratch (device globals; no cudaMalloc allowed)
__device__ float g_xw[(size_t)MROWS * G4];   // 268 MB: x @ Wx + b
__device__ unsigned g_count;                 // barrier arrive counter
__device__ unsigned g_sense;                 // barrier sense (monotonic)

// h exchanged in MMA A-fragment layout: [buf][mt][ktile][lane] -> uint4 (a0..a3)
__device__ uint4 g_hfragHI[2][2][32][32];
__device__ uint4 g_hfragLO[2][2][32][32];

// bf16 hi/lo split buffers for tensor-core phase 1
__device__ __nv_bfloat16 g_xhi[(size_t)MROWS * DD];
__device__ __nv_bfloat16 g_xlo[(size_t)MROWS * DD];
__device__ __nv_bfloat16 g_whi[(size_t)DD * G4];
__device__ __nv_bfloat16 g_wlo[(size_t)DD * G4];

// ---------------------------------------------------------------------------
// fp32 -> bf16 hi + lo split
// ---------------------------------------------------------------------------
__device__ __forceinline__ void split1(float v, __nv_bfloat16& h, __nv_bfloat16& l)
{
    h = __float2bfloat16(v);
    l = __float2bfloat16(v - __bfloat162float(h));
}

__global__ void __launch_bounds__(256) split_kernel_x(const float* __restrict__ src)
{
    size_t i = (size_t)blockIdx.x * blockDim.x + threadIdx.x;
    size_t n4 = (size_t)MROWS * DD / 4;
    if (i >= n4) return;
    float4 v = ((const float4*)src)[i];
    __nv_bfloat16 h0, h1, h2, h3, l0, l1, l2, l3;
    split1(v.x, h0, l0); split1(v.y, h1, l1);
    split1(v.z, h2, l2); split1(v.w, h3, l3);
    ((__nv_bfloat162*)g_xhi)[2 * i]     = __nv_bfloat162(h0, h1);
    ((__nv_bfloat162*)g_xhi)[2 * i + 1] = __nv_bfloat162(h2, h3);
    ((__nv_bfloat162*)g_xlo)[2 * i]     = __nv_bfloat162(l0, l1);
    ((__nv_bfloat162*)g_xlo)[2 * i + 1] = __nv_bfloat162(l2, l3);
}

__global__ void __launch_bounds__(256) split_kernel_w(const float* __restrict__ src)
{
    size_t i = (size_t)blockIdx.x * blockDim.x + threadIdx.x;
    size_t n4 = (size_t)DD * G4 / 4;
    if (i >= n4) return;
    float4 v = ((const float4*)src)[i];
    __nv_bfloat16 h0, h1, h2, h3, l0, l1, l2, l3;
    split1(v.x, h0, l0); split1(v.y, h1, l1);
    split1(v.z, h2, l2); split1(v.w, h3, l3);
    ((__nv_bfloat162*)g_whi)[2 * i]     = __nv_bfloat162(h0, h1);
    ((__nv_bfloat162*)g_whi)[2 * i + 1] = __nv_bfloat162(h2, h3);
    ((__nv_bfloat162*)g_wlo)[2 * i]     = __nv_bfloat162(l0, l1);
    ((__nv_bfloat162*)g_wlo)[2 * i + 1] = __nv_bfloat162(l2, l3);
}

// ---------------------------------------------------------------------------
// PTX wrappers
// ---------------------------------------------------------------------------
__device__ __forceinline__ void ldsm_x4(uint32_t& r0, uint32_t& r1, uint32_t& r2,
                                        uint32_t& r3, const void* p)
{
    uint32_t a = (uint32_t)__cvta_generic_to_shared(p);
    asm volatile("ldmatrix.sync.aligned.m8n8.x4.shared.b16 {%0,%1,%2,%3}, [%4];"
                 : "=r"(r0), "=r"(r1), "=r"(r2), "=r"(r3) : "r"(a));
}

__device__ __forceinline__ void ldsm_x4_t(uint32_t& r0, uint32_t& r1, uint32_t& r2,
                                          uint32_t& r3, const void* p)
{
    uint32_t a = (uint32_t)__cvta_generic_to_shared(p);
    asm volatile("ldmatrix.sync.aligned.m8n8.x4.trans.shared.b16 {%0,%1,%2,%3}, [%4];"
                 : "=r"(r0), "=r"(r1), "=r"(r2), "=r"(r3) : "r"(a));
}

__device__ __forceinline__ void mma_bf16(float* c, const uint32_t* a,
                                         uint32_t b0, uint32_t b1)
{
    asm volatile(
        "mma.sync.aligned.m16n8k16.row.col.f32.bf16.bf16.f32 "
        "{%0,%1,%2,%3},{%4,%5,%6,%7},{%8,%9},{%0,%1,%2,%3};"
        : "+f"(c[0]), "+f"(c[1]), "+f"(c[2]), "+f"(c[3])
        : "r"(a[0]), "r"(a[1]), "r"(a[2]), "r"(a[3]), "r"(b0), "r"(b1));
}

// ---------------------------------------------------------------------------
// Phase 1 GEMM on tensor cores (bf16 split) — unchanged from R3 (passing).
// ---------------------------------------------------------------------------
#define P1_SA 40
#define P1_SB 136

__global__ void __launch_bounds__(256, 2) gemm_xw_mma(const float* __restrict__ bias)
{
    __shared__ __nv_bfloat16 Ah[64 * P1_SA];
    __shared__ __nv_bfloat16 Al[64 * P1_SA];
    __shared__ __nv_bfloat16 Bh[32 * P1_SB];
    __shared__ __nv_bfloat16 Bl[32 * P1_SB];

    const int tid = threadIdx.x;
    const int bn = blockIdx.x;
    const int bm = blockIdx.y;
    const int warp = tid >> 5;
    const int lane = tid & 31;
    const int wm = (warp >> 2) * 32;
    const int wn = (warp & 3) * 32;

    const int arow = tid >> 2;
    const int acol = (tid & 3) * 8;
    const int brow = tid >> 4;
    const int bcol = (tid & 15) * 8;

    const size_t a_off = (size_t)(bm * 64 + arow) * DD + acol;
    const size_t b_off0 = (size_t)brow * G4 + bn * 128 + bcol;

    float acc[2][4][4];
#pragma unroll
    for (int mi = 0; mi < 2; mi++)
#pragma unroll
        for (int n = 0; n < 4; n++)
#pragma unroll
            for (int q = 0; q < 4; q++) acc[mi][n][q] = 0.0f;

    const int a_lrow = lane & 15;
    const int a_lcol = (lane >> 4) << 3;

    for (int k0 = 0; k0 < DD; k0 += 32) {
        *(uint4*)&Ah[arow * P1_SA + acol] = *(const uint4*)&g_xhi[a_off + k0];
        *(uint4*)&Al[arow * P1_SA + acol] = *(const uint4*)&g_xlo[a_off + k0];
#pragma unroll
        for (int i = 0; i < 2; i++) {
            size_t go = b_off0 + (size_t)(k0 + i * 16) * G4;
            *(uint4*)&Bh[(brow + i * 16) * P1_SB + bcol] = *(const uint4*)&g_whi[go];
            *(uint4*)&Bl[(brow + i * 16) * P1_SB + bcol] = *(const uint4*)&g_wlo[go];
        }
        __syncthreads();

#pragma unroll
        for (int kk = 0; kk < 32; kk += 16) {
            uint32_t ah[2][4], al[2][4], bh[2][4], bl[2][4];
#pragma unroll
            for (int mi = 0; mi < 2; mi++) {
                const __nv_bfloat16* pa =
                    &Ah[(wm + mi * 16 + a_lrow) * P1_SA + kk + a_lcol];
                ldsm_x4(ah[mi][0], ah[mi][1], ah[mi][2], ah[mi][3], pa);
                const __nv_bfloat16* pl =
                    &Al[(wm + mi * 16 + a_lrow) * P1_SA + kk + a_lcol];
                ldsm_x4(al[mi][0], al[mi][1], al[mi][2], al[mi][3], pl);
            }
#pragma unroll
            for (int g = 0; g < 2; g++) {
                const __nv_bfloat16* pb =
                    &Bh[(kk + a_lrow) * P1_SB + wn + g * 16 + a_lcol];
                ldsm_x4_t(bh[g][0], bh[g][1], bh[g][2], bh[g][3], pb);
                const __nv_bfloat16* pbl =
                    &Bl[(kk + a_lrow) * P1_SB + wn + g * 16 + a_lcol];
                ldsm_x4_t(bl[g][0], bl[g][1], bl[g][2], bl[g][3], pbl);
            }
#pragma unroll
            for (int mi = 0; mi < 2; mi++)
#pragma unroll
                for (int n = 0; n < 4; n++) {
                    uint32_t b0 = bh[n >> 1][(n & 1) * 2];
                    uint32_t b1 = bh[n >> 1][(n & 1) * 2 + 1];
                    uint32_t c0 = bl[n >> 1][(n & 1) * 2];
                    uint32_t c1 = bl[n >> 1][(n & 1) * 2 + 1];
                    mma_bf16(acc[mi][n], ah[mi], b0, b1);
                    mma_bf16(acc[mi][n], ah[mi], c0, c1);
                    mma_bf16(acc[mi][n], al[mi], b0, b1);
                }
        }
        __syncthreads();
    }

    const int r0 = bm * 64 + wm + (lane >> 2);
    const int c0 = bn * 128 + wn + (lane & 3) * 2;
#pragma unroll
    for (int mi = 0; mi < 2; mi++)
#pragma unroll
        for (int n = 0; n < 4; n++) {
            int col = c0 + n * 8;
            float bv0 = bias[col], bv1 = bias[col + 1];
            int row = r0 + mi * 16;
            float2 v0 = {acc[mi][n][0] + bv0, acc[mi][n][1] + bv1};
            float2 v1 = {acc[mi][n][2] + bv0, acc[mi][n][3] + bv1};
            *(float2*)&g_xw[(size_t)row * G4 + col] = v0;
            *(float2*)&g_xw[(size_t)(row + 8) * G4 + col] = v1;
        }
}

// ---------------------------------------------------------------------------
// Activations (fp32)
// ---------------------------------------------------------------------------
__device__ __forceinline__ float sigmoid_f(float x)
{
    float t = __expf(-fabsf(x));
    float inv = 1.0f / (1.0f + t);
    return (x >= 0.0f) ? inv : t * inv;
}

__device__ __forceinline__ float tanh_f(float x)
{
    float e = __expf(-2.0f * fabsf(x));
    float r = (1.0f - e) / (1.0f + e);
    return (x >= 0.0f) ? r : -r;
}

// ---------------------------------------------------------------------------
// Replay-safe grid barrier
// ---------------------------------------------------------------------------
__device__ __forceinline__ void grid_barrier(unsigned target)
{
    __syncthreads();
    if (threadIdx.x == 0) {
        unsigned old = atomicAdd(&g_count, 1u);
        if (old == RBLOCKS - 1) {
            atomicExch(&g_count, 0u);
            __threadfence();
            atomicAdd(&g_sense, 1u);
        } else {
            while ((int)(*(volatile unsigned*)&g_sense - target) < 0) { }
            __threadfence();
        }
    }
    __syncthreads();
}

// ---------------------------------------------------------------------------
// Phase 2: persistent recurrence on tensor cores.
// 128 blocks x 256 threads (8 warps). Block b owns gate cols c=0..15 packed as
// c = gate*4 + jl, global Wh col = gate*512 + 4b + jl. Warp w handles K-chunk
// [64w, 64w+64) = 4 k16-tiles. Wh B-fragments live in registers (hi/lo).
// h exchanged via g_hfrag (A-fragment layout), ping-pong buffers.
// ---------------------------------------------------------------------------
__global__ void __launch_bounds__(RTHREADS, 1)
lstm_rec_mma(const float* __restrict__ h0,
             const float* __restrict__ Wh,
             float* __restrict__ out)
{
    __shared__ float red[8][32][16];   // k-split partials
    __shared__ float a_s[512];         // reduced pre-activations [n][c]

    const int tid  = threadIdx.x;
    const int bid  = blockIdx.x;
    const int j0   = bid * JPB;
    const int w    = tid >> 5;
    const int lane = tid & 31;
    const int g    = lane >> 2;   // 0..7
    const int tig  = lane & 3;    // 0..3

    const unsigned sense0 = *(volatile unsigned*)&g_sense;
    unsigned nbar = 0;

    // ---- one-time: build Wh B-fragments in registers (hi/lo) ----
    uint2 bh[2][4], bl[2][4];
#pragma unroll
    for (int nt = 0; nt < 2; nt++) {
        int c = nt * 8 + g;                       // packed col 0..15
        int wcol = (c >> 2) * 512 + j0 + (c & 3); // global Wh column
#pragma unroll
        for (int kt = 0; kt < 4; kt++) {
            int k0 = (4 * w + kt) * 16;
            float w00 = Wh[(size_t)(k0 + 2 * tig) * G4 + wcol];
            float w01 = Wh[(size_t)(k0 + 2 * tig + 1) * G4 + wcol];
            float w10 = Wh[(size_t)(k0 + 8 + 2 * tig) * G4 + wcol];
            float w11 = Wh[(size_t)(k0 + 8 + 2 * tig + 1) * G4 + wcol];
            __nv_bfloat16 h00, h01, h10, h11, l00, l01, l10, l11;
            split1(w00, h00, l00); split1(w01, h01, l01);
            split1(w10, h10, l10); split1(w11, h11, l11);
            bh[nt][kt].x = ((uint32_t)__bfloat16_as_ushort(h01) << 16) |
                           __bfloat16_as_ushort(h00);
            bh[nt][kt].y = ((uint32_t)__bfloat16_as_ushort(h11) << 16) |
                           __bfloat16_as_ushort(h10);
            bl[nt][kt].x = ((uint32_t)__bfloat16_as_ushort(l01) << 16) |
                           __bfloat16_as_ushort(l00);
            bl[nt][kt].y = ((uint32_t)__bfloat16_as_ushort(l11) << 16) |
                           __bfloat16_as_ushort(l10);
        }
    }

    // ---- gate-thread geometry (tid < 64): owns (n, f0=j0+2*jlp, f0+1) ----
    const int gn   = tid >> 1;       // batch row 0..31
    const int jlp  = tid & 1;        // 0..1
    const int f0   = j0 + 2 * jlp;   // even global h column
    // fragment write coords for (gn, f0):
    const int w_mt   = gn >> 4;
    const int w_r    = gn & 15;
    const int w_ktg  = f0 >> 4;
    const int w_kc   = f0 & 15;
    const int w_lane = (w_r & 7) * 4 + ((w_kc & 7) >> 1);
    const int w_reg  = ((w_kc & 8) ? 2 : 0) + ((w_r & 8) ? 1 : 0);
    uint32_t* whi_p = (uint32_t*)&g_hfragHI[0][w_mt][w_ktg][w_lane] + w_reg;
    uint32_t* wlo_p = (uint32_t*)&g_hfragLO[0][w_mt][w_ktg][w_lane] + w_reg;
    const size_t fragbuf_stride = sizeof(g_hfragHI[0]) / 4;  // in uint32 units

    float c_st0 = 0.0f, c_st1 = 0.0f;  // cell state registers

    // ---- init h0 fragments (buffer 0) ----
    if (tid < 64) {
        float v0 = h0[(size_t)gn * HH + f0];
        float v1 = h0[(size_t)gn * HH + f0 + 1];
        __nv_bfloat16 h0b, h1b, l0b, l1b;
        split1(v0, h0b, l0b); split1(v1, h1b, l1b);
        *whi_p = ((uint32_t)__bfloat16_as_ushort(h1b) << 16) |
                 __bfloat16_as_ushort(h0b);
        *wlo_p = ((uint32_t)__bfloat16_as_ushort(l1b) << 16) |
                 __bfloat16_as_ushort(l0b);
    }
    __threadfence();
    grid_barrier(sense0 + (++nbar));

    // ---- xw prefetch mapping: thread reduces outputs o0=2tid, o0+1 ----
    const int o0 = 2 * tid;
    const int xn = o0 >> 4;
    const int xc0 = o0 & 15, xc1 = xc0 + 1;
    const size_t xw_base0 = (size_t)xn * TT * G4 + (xc0 >> 2) * 512 + j0 + (xc0 & 3);
    const size_t xw_base1 = (size_t)xn * TT * G4 + (xc1 >> 2) * 512 + j0 + (xc1 & 3);

    float xw0 = __ldcg(&g_xw[xw_base0]);
    float xw1 = __ldcg(&g_xw[xw_base1]);

    for (int t = 0; t < TT; t++) {
        // prefetch next step's xw (independent of h)
        int tn = (t + 1 < TT) ? t + 1 : t;
        float nxw0 = __ldcg(&g_xw[xw_base0 + (size_t)tn * G4]);
        float nxw1 = __ldcg(&g_xw[xw_base1 + (size_t)tn * G4]);

        // load h_t A-fragments (written by all SMs -> bypass L1)
        const int p = t & 1;
        uint4 ahi[2][4], alo[2][4];
#pragma unroll
        for (int mt = 0; mt < 2; mt++)
#pragma unroll
            for (int kt = 0; kt < 4; kt++) {
                ahi[mt][kt] = __ldcg(&g_hfragHI[p][mt][4 * w + kt][lane]);
                alo[mt][kt] = __ldcg(&g_hfragLO[p][mt][4 * w + kt][lane]);
            }

        // 3-term split MMA: acc = Ah*Bh + Ah*Bl + Al*Bh
        float acc[2][2][4];
#pragma unroll
        for (int mt = 0; mt < 2; mt++)
#pragma unroll
            for (int nt = 0; nt < 2; nt++)
#pragma unroll
                for (int q = 0; q < 4; q++) acc[mt][nt][q] = 0.0f;

#pragma unroll
        for (int kt = 0; kt < 4; kt++)
#pragma unroll
            for (int mt = 0; mt < 2; mt++)
#pragma unroll
                for (int nt = 0; nt < 2; nt++) {
                    mma_bf16(acc[mt][nt], (const uint32_t*)&ahi[mt][kt],
                             bh[nt][kt].x, bh[nt][kt].y);
                    mma_bf16(acc[mt][nt], (const uint32_t*)&ahi[mt][kt],
                             bl[nt][kt].x, bl[nt][kt].y);
                    mma_bf16(acc[mt][nt], (const uint32_t*)&alo[mt][kt],
                             bh[nt][kt].x, bh[nt][kt].y);
                }

        // store k-split partials
#pragma unroll
        for (int mt = 0; mt < 2; mt++)
#pragma unroll
            for (int nt = 0; nt < 2; nt++) {
                *(float2*)&red[w][mt * 16 + g][nt * 8 + tig * 2] =
                    make_float2(acc[mt][nt][0], acc[mt][nt][1]);
                *(float2*)&red[w][mt * 16 + g + 8][nt * 8 + tig * 2] =
                    make_float2(acc[mt][nt][2], acc[mt][nt][3]);
            }
        __syncthreads();

        // reduce 8 warps + xw -> a_s
        {
            float s0 = xw0, s1 = xw1;
#pragma unroll
            for (int ww = 0; ww < 8; ww++) {
                float2 r = *(const float2*)&red[ww][xn][xc0];
                s0 += r.x; s1 += r.y;
            }
            *(float2*)&a_s[o0] = make_float2(s0, s1);
        }
        __syncthreads();

        // gates: thread tid<64 handles (gn, f0) and (gn, f0+1)
        if (tid < 64) {
            const float* ap = &a_s[gn * CPB + 2 * jlp];
            float2 ai = *(const float2*)(ap + 0);
            float2 af = *(const float2*)(ap + 4);
            float2 ao = *(const float2*)(ap + 8);
            float2 ag = *(const float2*)(ap + 12);

            float i0 = sigmoid_f(ai.x), i1 = sigmoid_f(ai.y);
            float fg0 = sigmoid_f(af.x), fg1 = sigmoid_f(af.y);
            float oo0 = sigmoid_f(ao.x), oo1 = sigmoid_f(ao.y);
            float gg0 = tanh_f(ag.x),   gg1 = tanh_f(ag.y);

            c_st0 = fmaf(fg0, c_st0, i0 * gg0);
            c_st1 = fmaf(fg1, c_st1, i1 * gg1);
            float hn0 = oo0 * tanh_f(c_st0);
            float hn1 = oo1 * tanh_f(c_st1);

            // output (fp32)
            *(float2*)&out[((size_t)gn * TT + t) * HH + f0] = make_float2(hn0, hn1);

            // write h_{t+1} fragments (hi/lo) to buffer (t+1)&1
            __nv_bfloat16 hb0, hb1, lb0, lb1;
            split1(hn0, hb0, lb0); split1(hn1, hb1, lb1);
            size_t boff = (size_t)((t + 1) & 1) * fragbuf_stride;
            whi_p[boff] = ((uint32_t)__bfloat16_as_ushort(hb1) << 16) |
                          __bfloat16_as_ushort(hb0);
            wlo_p[boff] = ((uint32_t)__bfloat16_as_ushort(lb1) << 16) |
                          __bfloat16_as_ushort(lb0);
        }
        xw0 = nxw0; xw1 = nxw1;

        __threadfence();
        grid_barrier(sense0 + (++nbar));
    }
}

// ---------------------------------------------------------------------------
// kernel_launch
// ---------------------------------------------------------------------------
extern "C" void kernel_launch(void* const* d_in, const int* in_sizes, int n_in,
                              void* d_out, int out_size)
{
    const float* x  = (const float*)d_in[0];  // (32, 1024, 512)
    const float* h0 = (const float*)d_in[1];  // (32, 512)
    const float* Wx = (const float*)d_in[2];  // (512, 2048)
    const float* Wh = (const float*)d_in[3];  // (512, 2048)
    const float* b  = (const float*)d_in[4];  // (2048,)
    float* out = (float*)d_out;               // (32, 1024, 512)

    (void)in_sizes; (void)n_in; (void)out_size;

    // Phase 1: split + tensor-core GEMM
    size_t nx4 = (size_t)MROWS * DD / 4;
    size_t nw4 = (size_t)DD * G4 / 4;
    split_kernel_x<<<(unsigned)((nx4 + 255) / 256), 256>>>(x);
    split_kernel_w<<<(unsigned)((nw4 + 255) / 256), 256>>>(Wx);

    dim3 g1(G4 / 128, MROWS / 64);
    gemm_xw_mma<<<g1, 256>>>(b);

    // Phase 2: persistent tensor-core recurrence
    lstm_rec_mma<<<RBLOCKS, RTHREADS>>>(h0, Wh, out);
}